// round 7
// baseline (speedup 1.0000x reference)
#include <cuda_runtime.h>
#include <cstdint>

// Delta modulation encoder: 512 independent serial scans of length 131072.
// Bit-exact fp32 replication of:
//   err = fl(x_t - r); p = err>0.1; n = err<-0.1; spike = p-n; r = fl(r + spike*0.1)
//
// R6 lesson: FSETP->selp chain is 21 cyc (13-cyc predicate class dominates).
// R7: predicate-free integer chain:
//   mu = FFMA(E, -2^127, theta*2^127)   // sign(mu) == sign(theta-E), +0 iff E==theta
//   md = FFMA(E, +2^127, theta*2^127)   // sign(md) == sign(theta+E), +0 iff E==-theta
//   su = mu >> 31 (arith), sd = md >> 31        -> {0, -1} masks, strict ties exact
//   E' = LOP3(Ed, sd, LOP3(Eu, su, Ez))          -> exact bit select
// Chain: FFMA(4) -> SAR(4) -> LOP3(4) -> LOP3(4) = 16 cyc/step, all fixed-lat.
// recon & candidates resolved off-chain (FADDs with reference rounding order).

constexpr int T_LEN = 131072;
constexpr int NSEQ  = 512;            // 64 * 8
constexpr int TILE  = 128;            // time steps per lane per tile
constexpr int NT    = T_LEN / TILE;   // 1024 tiles
constexpr int ROWF  = TILE + 4;       // 132 floats = 528B stride (33*16B -> conflict-free)
constexpr int NBUF  = 3;              // input ring: t, t+1 resident, t+2 in flight
constexpr int GRP   = TILE / 4;       // 32 float4 groups per tile

constexpr int SIN_ELEMS  = 32 * ROWF;                   // per buffer
constexpr int SMEM_BYTES = (NBUF + 2) * SIN_ELEMS * 4;  // 3 in + 2 out = 84480 B

struct DM {
    uint32_t mu, md;          // chain guards (bits of signed-huge floats)
    uint32_t rrb;             // recon bits
    uint32_t Eu, Ed, Ez;      // candidate next-err bits
    uint32_t ru, rd;          // candidate next-recon bits (rz == rrb)
};

// One element. xnn = x[t+2]. Returns spike_t bits (1.0f / -1.0f / +0.0f). Bit-exact.
__device__ __forceinline__ uint32_t dm_step(DM& s, float xnn) {
    uint32_t spike;
    asm("{\n\t"
        ".reg .b32 su, sd, t1, e, t2, ta;\n\t"
        ".reg .f32 ef, muf, mdf, rrf, ruf, rdf, euf, edf, ezf;\n\t"
        "shr.s32 su, %1, 31;\n\t"                         // -1 iff E >  theta
        "shr.s32 sd, %2, 31;\n\t"                         // -1 iff E < -theta
        "lop3.b32 t1, %4, su, %6, 0xE2;\n\t"              // su ? Eu : Ez
        "lop3.b32 e,  %5, sd, t1, 0xE2;\n\t"              // sd ? Ed : t1   = E_{t+1}
        "mov.b32 ef, e;\n\t"
        "fma.rn.f32 muf, ef, 0fFF000000, 0f7D4CCCCD;\n\t" // (theta-E')*2^127
        "fma.rn.f32 mdf, ef, 0f7F000000, 0f7D4CCCCD;\n\t" // (theta+E')*2^127
        "mov.b32 %1, muf;\n\t"
        "mov.b32 %2, mdf;\n\t"
        "lop3.b32 t2, %7, su, %3, 0xE2;\n\t"              // su ? ru : rr
        "lop3.b32 %3, %8, sd, t2, 0xE2;\n\t"              // rr' = sd ? rd : t2
        "and.b32 ta, su, 0x3F800000;\n\t"
        "lop3.b32 %0, ta, sd, 0xBF800000, 0xF8;\n\t"      // spike bits = ta | (sd & -1.0f)
        "mov.b32 rrf, %3;\n\t"
        "add.f32 ruf, rrf, 0f3DCCCCCD;\n\t"               // fl(rr' + 0.1f)
        "add.f32 rdf, rrf, 0fBDCCCCCD;\n\t"               // fl(rr' - 0.1f)
        "sub.f32 euf, %9, ruf;\n\t"                       // fl(x'' - ru)
        "sub.f32 edf, %9, rdf;\n\t"
        "sub.f32 ezf, %9, rrf;\n\t"
        "mov.b32 %4, euf;\n\t"
        "mov.b32 %5, edf;\n\t"
        "mov.b32 %6, ezf;\n\t"
        "mov.b32 %7, ruf;\n\t"
        "mov.b32 %8, rdf;\n\t"
        "}"
        : "=r"(spike), "+r"(s.mu), "+r"(s.md), "+r"(s.rrb),
          "+r"(s.Eu), "+r"(s.Ed), "+r"(s.Ez), "+r"(s.ru), "+r"(s.rd)
        : "f"(xnn));
    return spike;
}

__device__ __forceinline__ void cp_async16(uint32_t dst_smem, const void* src) {
    asm volatile("cp.async.cg.shared.global [%0], [%1], 16;"
                 :: "r"(dst_smem), "l"(src));
}
__device__ __forceinline__ void cp_commit() {
    asm volatile("cp.async.commit_group;" ::: "memory");
}
__device__ __forceinline__ void cp_wait1() {
    asm volatile("cp.async.wait_group 1;" ::: "memory");
}
__device__ __forceinline__ void bar1() {
    asm volatile("bar.sync 1, 64;" ::: "memory");
}
__device__ __forceinline__ void bar2() {
    asm volatile("bar.sync 2, 64;" ::: "memory");
}

__global__ __launch_bounds__(64, 1)
void DeltaModulationEncoder_kernel(const float* __restrict__ x,
                                   float* __restrict__ out) {
    extern __shared__ float smem[];
    float* sin_buf[NBUF];
#pragma unroll
    for (int b = 0; b < NBUF; b++) sin_buf[b] = smem + b * SIN_ELEMS;
    float* sout0 = smem + NBUF * SIN_ELEMS;
    float* sout1 = sout0 + SIN_ELEMS;

    const int tid  = threadIdx.x;
    const int warp = tid >> 5;
    const int lane = tid & 31;
    const int seqbase = blockIdx.x * 32;

    if (warp == 1) {
        // ───────────────────────── I/O warp ─────────────────────────
        // One cp.async / LDS+STG instruction per ROW: row i's 512B tile chunk,
        // lane covers byte lane*16 -> fully coalesced.
        const char* gsrc = (const char*)(x + (size_t)seqbase * T_LEN) + lane * 16;
        char*       gdst = (char*)(out + (size_t)seqbase * T_LEN) + lane * 16;
        const size_t rowstride = (size_t)T_LEN * 4;

        uint32_t sin_addr[NBUF];
#pragma unroll
        for (int b = 0; b < NBUF; b++)
            sin_addr[b] = (uint32_t)__cvta_generic_to_shared(sin_buf[b])
                        + (uint32_t)(lane * 16);

#pragma unroll
        for (int t0 = 0; t0 < 2; t0++) {
            const char* g = gsrc + (size_t)t0 * TILE * 4;
            const uint32_t s = sin_addr[t0];
#pragma unroll
            for (int i = 0; i < 32; i++)
                cp_async16(s + (uint32_t)(i * ROWF * 4), g + (size_t)i * rowstride);
            cp_commit();
        }

        int slot_w = 2;
        for (int t = 0; t < NT; ++t) {
            if (t + 2 < NT) {
                const char* g = gsrc + (size_t)(t + 2) * TILE * 4;
                const uint32_t s = sin_addr[slot_w];
#pragma unroll
                for (int i = 0; i < 32; i++)
                    cp_async16(s + (uint32_t)(i * ROWF * 4), g + (size_t)i * rowstride);
            }
            cp_commit();
            cp_wait1();                 // tiles t, t+1 resident
            bar1();                     // release compute for tile t

            if (t > 0) {                // flush sout[(t-1)&1]
                const float* sob = ((t - 1) & 1 ? sout1 : sout0) + (lane * 4);
                char* g = gdst + (size_t)(t - 1) * TILE * 4;
#pragma unroll
                for (int i = 0; i < 32; i++) {
                    float4 v = *(const float4*)(sob + i * ROWF);
                    *(float4*)(g + (size_t)i * rowstride) = v;
                }
            }
            bar2();                     // buffer reusable; tile t STS visible
            slot_w = (slot_w + 1 == NBUF) ? 0 : slot_w + 1;
        }
        {
            const float* sob = ((NT - 1) & 1 ? sout1 : sout0) + (lane * 4);
            char* g = gdst + (size_t)(NT - 1) * TILE * 4;
#pragma unroll
            for (int i = 0; i < 32; i++) {
                float4 v = *(const float4*)(sob + i * ROWF);
                *(float4*)(g + (size_t)i * rowstride) = v;
            }
        }
    } else {
        // ──────────────────────── compute warp ────────────────────────
        DM st;
        int s0 = 0;
        for (int t = 0; t < NT; ++t) {
            const int s1 = (s0 + 1 == NBUF) ? 0 : s0 + 1;
            bar1();                     // tiles t (slot s0), t+1 (slot s1) resident

            if (t == 0) {               // recon r0 = +0
                const float x0 = sin_buf[0][lane * ROWF + 0];
                const float x1 = sin_buf[0][lane * ROWF + 1];
                const float big  = __uint_as_float(0x7F000000);   // 2^127
                const float thrs = __uint_as_float(0x7D4CCCCD);   // 0.1f * 2^127
                st.mu  = __float_as_uint(__fmaf_rn(x0, -big, thrs));
                st.md  = __float_as_uint(__fmaf_rn(x0,  big, thrs));
                st.rrb = 0u;                                      // +0.0f
                st.ru  = 0x3DCCCCCDu;                             //  0.1f
                st.rd  = 0xBDCCCCCDu;                             // -0.1f
                st.Eu  = __float_as_uint(x1 - 0.1f);
                st.Ed  = __float_as_uint(x1 + 0.1f);
                st.Ez  = __float_as_uint(x1);
            }

            const float4* bk  = (const float4*)(sin_buf[s0] + lane * ROWF);
            const float4* bk1 = (const float4*)(sin_buf[s1] + lane * ROWF);
            uint4* so = (uint4*)((t & 1 ? sout1 : sout0) + lane * ROWF);

            float4 cur = bk[0];
            float4 nxt = bk[1];
#pragma unroll
            for (int g = 0; g < GRP; ++g) {
                // group g+2 (peeks into tile t+1 for g >= GRP-2; past the last
                // tile this is stale smem feeding only never-output candidates)
                const float4 nn = (g < GRP - 2) ? bk[g + 2] : bk1[g - (GRP - 2)];

                uint4 sp;
                sp.x = dm_step(st, cur.z);
                sp.y = dm_step(st, cur.w);
                sp.z = dm_step(st, nxt.x);
                sp.w = dm_step(st, nxt.y);
                so[g] = sp;             // STS.128, conflict-free

                cur = nxt;
                nxt = nn;
            }
            bar2();                     // hand buffer t&1 to the I/O warp
            s0 = s1;
        }
    }
}

extern "C" void kernel_launch(void* const* d_in, const int* in_sizes, int n_in,
                              void* d_out, int out_size) {
    (void)in_sizes; (void)n_in; (void)out_size;
    const float* x = (const float*)d_in[0];
    float* out     = (float*)d_out;

    cudaFuncSetAttribute(DeltaModulationEncoder_kernel,
                         cudaFuncAttributeMaxDynamicSharedMemorySize, SMEM_BYTES);
    DeltaModulationEncoder_kernel<<<NSEQ / 32, 64, SMEM_BYTES>>>(x, out);
}

// round 8
// speedup vs baseline: 1.6079x; 1.6079x over previous
#include <cuda_runtime.h>
#include <cstdint>

// Delta modulation encoder: 512 independent serial scans of length 131072.
// Bit-exact fp32 replication of:
//   err = fl(x_t - r); p = err>0.1; n = err<-0.1; spike = p-n; r = fl(r + spike*0.1)
//
// R7 lesson: integer-domain chain regressed (real MOVs between fp/int classes).
// Revert to R6's 12-op setp/selp step (best measured).
// R8 experiment: the chip appears DVFS-limited (~1.2 GHz) at 16 active SMs.
// Reshape to 128 blocks x 4 sequences/warp: identical SIMD instruction stream
// per step (same cycle count), 8x more active SMs -> let the clock ramp.

constexpr int T_LEN = 131072;
constexpr int NSEQ  = 512;            // 64 * 8
constexpr int SEQ_B = 4;              // sequences per block
constexpr int TILE  = 128;            // time steps per lane per tile
constexpr int NT    = T_LEN / TILE;   // 1024 tiles
constexpr int ROWF  = TILE + 4;       // 132 floats = 528B stride
constexpr int NBUF  = 3;              // input ring: t, t+1 resident, t+2 in flight
constexpr int GRP   = TILE / 4;       // 32 float4 groups per tile

struct DMState {
    float err;              // resolved err_t (chain state)
    float rr;               // resolved recon
    float Eu, Ed, Ez;       // x_{t+1} - {fl(rr+0.1), fl(rr-0.1), rr}
};

// One element. xnn = x[t+2]. Returns spike_t in {-1,0,1}. Bit-exact.
__device__ __forceinline__ float dm_step(DMState& s, float xnn) {
    float spike;
    asm("{\n\t"
        ".reg .pred p, n;\n\t"
        ".reg .f32  t0, t1, cu, cd;\n\t"
        "setp.gt.f32 p, %1, 0f3DCCCCCD;\n\t"            // err >  0.1f
        "setp.lt.f32 n, %1, 0fBDCCCCCD;\n\t"            // err < -0.1f
        "selp.f32 t0, 0fBF800000, 0f00000000, n;\n\t"   // n ? -1 : 0
        "selp.f32 %0, 0f3F800000, t0, p;\n\t"           // spike
        "selp.f32 t1, %4, %5, n;\n\t"                   // n ? Ed : Ez
        "selp.f32 %1, %3, t1, p;\n\t"                   // err' (chain)
        "fma.rn.f32 %2, %0, 0f3DCCCCCD, %2;\n\t"        // rr' = fl(rr + spike*0.1f)
        "add.f32  cu, %2, 0f3DCCCCCD;\n\t"              // fl(rr'+0.1f)
        "add.f32  cd, %2, 0fBDCCCCCD;\n\t"              // fl(rr'-0.1f)
        "sub.f32  %3, %6, cu;\n\t"                      // Eu'
        "sub.f32  %4, %6, cd;\n\t"                      // Ed'
        "sub.f32  %5, %6, %2;\n\t"                      // Ez'
        "}"
        : "=f"(spike),
          "+f"(s.err), "+f"(s.rr),
          "+f"(s.Eu), "+f"(s.Ed), "+f"(s.Ez)
        : "f"(xnn));
    return spike;
}

__device__ __forceinline__ void cp_async16(uint32_t dst_smem, const void* src) {
    asm volatile("cp.async.cg.shared.global [%0], [%1], 16;"
                 :: "r"(dst_smem), "l"(src));
}
__device__ __forceinline__ void cp_commit() {
    asm volatile("cp.async.commit_group;" ::: "memory");
}
__device__ __forceinline__ void cp_wait1() {
    asm volatile("cp.async.wait_group 1;" ::: "memory");
}
__device__ __forceinline__ void bar1() {
    asm volatile("bar.sync 1, 64;" ::: "memory");
}
__device__ __forceinline__ void bar2() {
    asm volatile("bar.sync 2, 64;" ::: "memory");
}

__global__ __launch_bounds__(64, 1)
void DeltaModulationEncoder_kernel(const float* __restrict__ x,
                                   float* __restrict__ out) {
    // 4 rows per tile buffer: 3 in-ring + 2 out = 10.5 KB static smem.
    __shared__ __align__(16) float sin_buf[NBUF][SEQ_B * ROWF];
    __shared__ __align__(16) float sout[2][SEQ_B * ROWF];

    const int tid  = threadIdx.x;
    const int warp = tid >> 5;
    const int lane = tid & 31;
    const int seqbase = blockIdx.x * SEQ_B;

    if (warp == 1) {
        // ───────────────────────── I/O warp ─────────────────────────
        // Per tile: 4 rows x 512B. Instruction i covers row i; lane covers
        // byte lane*16 within the row -> one fully-coalesced 512B op per row.
        const size_t rowstride = (size_t)T_LEN * 4;
        const char* gsrc = (const char*)(x + (size_t)seqbase * T_LEN) + lane * 16;
        char*       gdst = (char*)(out + (size_t)seqbase * T_LEN) + lane * 16;

        uint32_t sin_addr[NBUF];
#pragma unroll
        for (int b = 0; b < NBUF; b++)
            sin_addr[b] = (uint32_t)__cvta_generic_to_shared(&sin_buf[b][0])
                        + (uint32_t)(lane * 16);

#pragma unroll
        for (int t0 = 0; t0 < 2; t0++) {
            const char* g = gsrc + (size_t)t0 * TILE * 4;
            const uint32_t s = sin_addr[t0];
#pragma unroll
            for (int i = 0; i < SEQ_B; i++)
                cp_async16(s + (uint32_t)(i * ROWF * 4), g + (size_t)i * rowstride);
            cp_commit();
        }

        int slot_w = 2;
        for (int t = 0; t < NT; ++t) {
            if (t + 2 < NT) {
                const char* g = gsrc + (size_t)(t + 2) * TILE * 4;
                const uint32_t s = sin_addr[slot_w];
#pragma unroll
                for (int i = 0; i < SEQ_B; i++)
                    cp_async16(s + (uint32_t)(i * ROWF * 4), g + (size_t)i * rowstride);
            }
            cp_commit();
            cp_wait1();                 // tiles t, t+1 resident
            bar1();                     // release compute for tile t

            if (t > 0) {                // flush sout[(t-1)&1]
                const float* sob = &sout[(t - 1) & 1][0] + lane * 4;
                char* g = gdst + (size_t)(t - 1) * TILE * 4;
#pragma unroll
                for (int i = 0; i < SEQ_B; i++) {
                    float4 v = *(const float4*)(sob + i * ROWF);
                    *(float4*)(g + (size_t)i * rowstride) = v;
                }
            }
            bar2();                     // buffer reusable; tile t STS visible
            slot_w = (slot_w + 1 == NBUF) ? 0 : slot_w + 1;
        }
        {
            const float* sob = &sout[(NT - 1) & 1][0] + lane * 4;
            char* g = gdst + (size_t)(NT - 1) * TILE * 4;
#pragma unroll
            for (int i = 0; i < SEQ_B; i++) {
                float4 v = *(const float4*)(sob + i * ROWF);
                *(float4*)(g + (size_t)i * rowstride) = v;
            }
        }
    } else {
        // ──────────────────────── compute warp ────────────────────────
        // 4 real sequences; lanes 4-31 duplicate lanes 0-3 (stores masked).
        const int row = lane & (SEQ_B - 1);
        const bool writer = (lane < SEQ_B);

        DMState st;
        int s0 = 0;
        for (int t = 0; t < NT; ++t) {
            const int s1 = (s0 + 1 == NBUF) ? 0 : s0 + 1;
            bar1();                     // tiles t (slot s0), t+1 (slot s1) resident

            if (t == 0) {               // recon r0 = 0
                const float x0 = sin_buf[0][row * ROWF + 0];
                const float x1 = sin_buf[0][row * ROWF + 1];
                st.err = x0;
                st.rr  = 0.0f;
                st.Eu  = x1 - 0.1f;     // fl(x1 - fl(0+0.1))
                st.Ed  = x1 + 0.1f;     // fl(x1 - fl(0-0.1))
                st.Ez  = x1;            // fl(x1 - 0)
            }

            const float4* bk  = (const float4*)(&sin_buf[s0][0] + row * ROWF);
            const float4* bk1 = (const float4*)(&sin_buf[s1][0] + row * ROWF);
            float4* so = (float4*)(&sout[t & 1][0] + row * ROWF);

            float4 cur = bk[0];
            float4 nxt = bk[1];
#pragma unroll
            for (int g = 0; g < GRP; ++g) {
                // group g+2 (peeks into tile t+1 for g >= GRP-2; past the last
                // tile this is stale smem feeding only never-output candidates)
                const float4 nn = (g < GRP - 2) ? bk[g + 2] : bk1[g - (GRP - 2)];

                float4 sp;
                sp.x = dm_step(st, cur.z);
                sp.y = dm_step(st, cur.w);
                sp.z = dm_step(st, nxt.x);
                sp.w = dm_step(st, nxt.y);
                if (writer) so[g] = sp;   // predicated STS.128, lanes 0-3 only

                cur = nxt;
                nxt = nn;
            }
            bar2();                     // hand buffer t&1 to the I/O warp
            s0 = s1;
        }
    }
}

extern "C" void kernel_launch(void* const* d_in, const int* in_sizes, int n_in,
                              void* d_out, int out_size) {
    (void)in_sizes; (void)n_in; (void)out_size;
    const float* x = (const float*)d_in[0];
    float* out     = (float*)d_out;

    // 128 blocks x (1 compute warp + 1 I/O warp), 4 sequences per block.
    // One wave on 148 SMs; same per-warp cycle count as the 16-block layout,
    // 8x the active-SM utilization -> DVFS probe.
    DeltaModulationEncoder_kernel<<<NSEQ / SEQ_B, 64>>>(x, out);
}

// round 9
// speedup vs baseline: 1.6247x; 1.0105x over previous
#include <cuda_runtime.h>
#include <cstdint>

// Delta modulation encoder: 512 independent serial scans of length 131072.
// Bit-exact fp32 replication of:
//   err = fl(x_t - r); p = err>0.1; n = err<-0.1; spike = p-n; r = fl(r + spike*0.1)
//
// R8 lesson: identical per-warp code, 8x more active SMs -> 1.29x (DVFS ramps
// with utilization). R9: raise utilization 4x more — 4 compute warps per block
// (one sequence per warp, all 4 SMSPs busy) + 1 I/O warp. Per-warp instruction
// stream per step is unchanged; only chip-level activity (and thus clock) rises.

constexpr int T_LEN = 131072;
constexpr int NSEQ  = 512;            // 64 * 8
constexpr int SEQ_B = 4;              // sequences per block (one per compute warp)
constexpr int TILE  = 128;            // time steps per lane per tile
constexpr int NT    = T_LEN / TILE;   // 1024 tiles
constexpr int ROWF  = TILE + 4;       // 132 floats = 528B stride
constexpr int NBUF  = 3;              // input ring: t, t+1 resident, t+2 in flight
constexpr int GRP   = TILE / 4;       // 32 float4 groups per tile
constexpr int NTHREADS = 160;         // 4 compute warps + 1 I/O warp

struct DMState {
    float err;              // resolved err_t (chain state)
    float rr;               // resolved recon
    float Eu, Ed, Ez;       // x_{t+1} - {fl(rr+0.1), fl(rr-0.1), rr}
};

// One element. xnn = x[t+2]. Returns spike_t in {-1,0,1}. Bit-exact.
__device__ __forceinline__ float dm_step(DMState& s, float xnn) {
    float spike;
    asm("{\n\t"
        ".reg .pred p, n;\n\t"
        ".reg .f32  t0, t1, cu, cd;\n\t"
        "setp.gt.f32 p, %1, 0f3DCCCCCD;\n\t"            // err >  0.1f
        "setp.lt.f32 n, %1, 0fBDCCCCCD;\n\t"            // err < -0.1f
        "selp.f32 t0, 0fBF800000, 0f00000000, n;\n\t"   // n ? -1 : 0
        "selp.f32 %0, 0f3F800000, t0, p;\n\t"           // spike
        "selp.f32 t1, %4, %5, n;\n\t"                   // n ? Ed : Ez
        "selp.f32 %1, %3, t1, p;\n\t"                   // err' (chain)
        "fma.rn.f32 %2, %0, 0f3DCCCCCD, %2;\n\t"        // rr' = fl(rr + spike*0.1f)
        "add.f32  cu, %2, 0f3DCCCCCD;\n\t"              // fl(rr'+0.1f)
        "add.f32  cd, %2, 0fBDCCCCCD;\n\t"              // fl(rr'-0.1f)
        "sub.f32  %3, %6, cu;\n\t"                      // Eu'
        "sub.f32  %4, %6, cd;\n\t"                      // Ed'
        "sub.f32  %5, %6, %2;\n\t"                      // Ez'
        "}"
        : "=f"(spike),
          "+f"(s.err), "+f"(s.rr),
          "+f"(s.Eu), "+f"(s.Ed), "+f"(s.Ez)
        : "f"(xnn));
    return spike;
}

__device__ __forceinline__ void cp_async16(uint32_t dst_smem, const void* src) {
    asm volatile("cp.async.cg.shared.global [%0], [%1], 16;"
                 :: "r"(dst_smem), "l"(src));
}
__device__ __forceinline__ void cp_commit() {
    asm volatile("cp.async.commit_group;" ::: "memory");
}
__device__ __forceinline__ void cp_wait1() {
    asm volatile("cp.async.wait_group 1;" ::: "memory");
}
__device__ __forceinline__ void bar1() {
    asm volatile("bar.sync 1, %0;" :: "n"(NTHREADS) : "memory");
}
__device__ __forceinline__ void bar2() {
    asm volatile("bar.sync 2, %0;" :: "n"(NTHREADS) : "memory");
}

__global__ __launch_bounds__(NTHREADS, 1)
void DeltaModulationEncoder_kernel(const float* __restrict__ x,
                                   float* __restrict__ out) {
    // 4 rows per tile buffer: 3 in-ring + 2 out = ~10.5 KB static smem.
    __shared__ __align__(16) float sin_buf[NBUF][SEQ_B * ROWF];
    __shared__ __align__(16) float sout[2][SEQ_B * ROWF];

    const int tid  = threadIdx.x;
    const int warp = tid >> 5;
    const int lane = tid & 31;
    const int seqbase = blockIdx.x * SEQ_B;

    if (warp == 4) {
        // ───────────────────────── I/O warp ─────────────────────────
        // Per tile: 4 rows x 512B. Instruction i covers row i; lane covers
        // byte lane*16 within the row -> fully coalesced 512B per op.
        const size_t rowstride = (size_t)T_LEN * 4;
        const char* gsrc = (const char*)(x + (size_t)seqbase * T_LEN) + lane * 16;
        char*       gdst = (char*)(out + (size_t)seqbase * T_LEN) + lane * 16;

        uint32_t sin_addr[NBUF];
#pragma unroll
        for (int b = 0; b < NBUF; b++)
            sin_addr[b] = (uint32_t)__cvta_generic_to_shared(&sin_buf[b][0])
                        + (uint32_t)(lane * 16);

#pragma unroll
        for (int t0 = 0; t0 < 2; t0++) {
            const char* g = gsrc + (size_t)t0 * TILE * 4;
            const uint32_t s = sin_addr[t0];
#pragma unroll
            for (int i = 0; i < SEQ_B; i++)
                cp_async16(s + (uint32_t)(i * ROWF * 4), g + (size_t)i * rowstride);
            cp_commit();
        }

        int slot_w = 2;
        for (int t = 0; t < NT; ++t) {
            if (t + 2 < NT) {
                const char* g = gsrc + (size_t)(t + 2) * TILE * 4;
                const uint32_t s = sin_addr[slot_w];
#pragma unroll
                for (int i = 0; i < SEQ_B; i++)
                    cp_async16(s + (uint32_t)(i * ROWF * 4), g + (size_t)i * rowstride);
            }
            cp_commit();
            cp_wait1();                 // tiles t, t+1 resident
            bar1();                     // release compute for tile t

            if (t > 0) {                // flush sout[(t-1)&1]
                const float* sob = &sout[(t - 1) & 1][0] + lane * 4;
                char* g = gdst + (size_t)(t - 1) * TILE * 4;
#pragma unroll
                for (int i = 0; i < SEQ_B; i++) {
                    float4 v = *(const float4*)(sob + i * ROWF);
                    *(float4*)(g + (size_t)i * rowstride) = v;
                }
            }
            bar2();                     // buffer reusable; tile t STS visible
            slot_w = (slot_w + 1 == NBUF) ? 0 : slot_w + 1;
        }
        {
            const float* sob = &sout[(NT - 1) & 1][0] + lane * 4;
            char* g = gdst + (size_t)(NT - 1) * TILE * 4;
#pragma unroll
            for (int i = 0; i < SEQ_B; i++) {
                float4 v = *(const float4*)(sob + i * ROWF);
                *(float4*)(g + (size_t)i * rowstride) = v;
            }
        }
    } else {
        // ──────────────────────── compute warps 0-3 ────────────────────────
        // Warp w owns sequence row w; lanes 1-31 duplicate lane 0 (stores masked).
        const int row = warp;
        const bool writer = (lane == 0);

        DMState st;
        int s0 = 0;
        for (int t = 0; t < NT; ++t) {
            const int s1 = (s0 + 1 == NBUF) ? 0 : s0 + 1;
            bar1();                     // tiles t (slot s0), t+1 (slot s1) resident

            if (t == 0) {               // recon r0 = 0
                const float x0 = sin_buf[0][row * ROWF + 0];
                const float x1 = sin_buf[0][row * ROWF + 1];
                st.err = x0;
                st.rr  = 0.0f;
                st.Eu  = x1 - 0.1f;     // fl(x1 - fl(0+0.1))
                st.Ed  = x1 + 0.1f;     // fl(x1 - fl(0-0.1))
                st.Ez  = x1;            // fl(x1 - 0)
            }

            const float4* bk  = (const float4*)(&sin_buf[s0][0] + row * ROWF);
            const float4* bk1 = (const float4*)(&sin_buf[s1][0] + row * ROWF);
            float4* so = (float4*)(&sout[t & 1][0] + row * ROWF);

            float4 cur = bk[0];
            float4 nxt = bk[1];
#pragma unroll
            for (int g = 0; g < GRP; ++g) {
                // group g+2 (peeks into tile t+1 for g >= GRP-2; past the last
                // tile this is stale smem feeding only never-output candidates)
                const float4 nn = (g < GRP - 2) ? bk[g + 2] : bk1[g - (GRP - 2)];

                float4 sp;
                sp.x = dm_step(st, cur.z);
                sp.y = dm_step(st, cur.w);
                sp.z = dm_step(st, nxt.x);
                sp.w = dm_step(st, nxt.y);
                if (writer) so[g] = sp;   // predicated STS.128, lane 0 only

                cur = nxt;
                nxt = nn;
            }
            bar2();                     // hand buffer t&1 to the I/O warp
            s0 = s1;
        }
    }
}

extern "C" void kernel_launch(void* const* d_in, const int* in_sizes, int n_in,
                              void* d_out, int out_size) {
    (void)in_sizes; (void)n_in; (void)out_size;
    const float* x = (const float*)d_in[0];
    float* out     = (float*)d_out;

    // 128 blocks x (4 compute warps + 1 I/O warp), 1 sequence per compute warp.
    // All 4 SMSPs of ~128 SMs busy -> utilization/DVFS probe, cycles unchanged.
    DeltaModulationEncoder_kernel<<<NSEQ / SEQ_B, NTHREADS>>>(x, out);
}